// round 1
// baseline (speedup 1.0000x reference)
#include <cuda_runtime.h>
#include <math.h>

// Problem constants
#define BATCH   4096
#define HID     512
#define CARNUM  32
#define SEQLEN  33      // 32 vehicles + 1 main
#define TDEC    60
#define XROW    198     // 6 + 32*6

// GEMM tiling
#define BM 128
#define BN 64
#define BK 16

// ---------------- scratch (device globals; no allocation allowed) -------------
__device__ float g_h[2 * 2 * BATCH * HID];    // [parity][layer][B*H]
__device__ float g_xt[BATCH * HID];           // current embedded timestep
__device__ float g_relu[BATCH * HID];         // head hidden
__device__ float g_WT[9 * HID * HID];         // transposed weights
__device__ float g_bias[4 * HID];             // bih+bhh: enc l0, enc l1, dec l0, dec l1

struct Ptr9 { const float* p[9]; };

// ---------------- helper kernels ---------------------------------------------
__global__ void zero_kernel(float* __restrict__ p, int n) {
    for (int i = blockIdx.x * blockDim.x + threadIdx.x; i < n; i += gridDim.x * blockDim.x)
        p[i] = 0.f;
}

// WT[k][h] = W[h][k] for 9 512x512 matrices
__global__ void transpose_kernel(Ptr9 s, float* __restrict__ dst) {
    __shared__ float tile[32][33];
    int m = blockIdx.z;
    const float* src = s.p[m];
    int x0 = blockIdx.x * 32, y0 = blockIdx.y * 32;
    for (int j = threadIdx.y; j < 32; j += 8)
        tile[j][threadIdx.x] = src[(y0 + j) * HID + x0 + threadIdx.x];
    __syncthreads();
    float* d = dst + (size_t)m * HID * HID;
    for (int j = threadIdx.y; j < 32; j += 8)
        d[(size_t)(x0 + j) * HID + y0 + threadIdx.x] = tile[threadIdx.x][j];
}

__global__ void bias_kernel(const float* __restrict__ ebih, const float* __restrict__ ebhh,
                            const float* __restrict__ dbih, const float* __restrict__ dbhh,
                            float* __restrict__ out) {
    int i = blockIdx.x * blockDim.x + threadIdx.x;  // 0..2047
    if (i < 1024)       out[i] = ebih[i] + ebhh[i];
    else if (i < 2048)  out[i] = dbih[i - 1024] + dbhh[i - 1024];
}

// seq_t[b][e] = tanh(x_slice @ W^T + b)   (t<32: vehicle t, t==32: main)
__global__ void embed_kernel(const float* __restrict__ x,
                             const float* __restrict__ Wm, const float* __restrict__ bm,
                             const float* __restrict__ Wv, const float* __restrict__ bv,
                             int t, float* __restrict__ out) {
    int b = blockIdx.x;
    int e = threadIdx.x;
    const float* W; const float* bb; const float* xin;
    if (t < CARNUM) { W = Wv; bb = bv; xin = &x[b * XROW + 6 + 6 * t]; }
    else            { W = Wm; bb = bm; xin = &x[b * XROW]; }
    float s = bb[e];
#pragma unroll
    for (int j = 0; j < 6; ++j) s += xin[j] * W[e * 6 + j];
    out[b * HID + e] = tanhf(s);
}

// C[M,512] = act( A1@B1 + (A2?A2@B2:0) + bias ),  M=4096, K=512 per pair
// act: 1 = tanh, 2 = relu
__global__ __launch_bounds__(256)
void gemm_kernel(const float* __restrict__ A1, const float* __restrict__ B1,
                 const float* __restrict__ A2, const float* __restrict__ B2,
                 const float* __restrict__ bias, float* __restrict__ C, int act) {
    __shared__ float As[BK][BM];   // transposed A tile
    __shared__ float Bs[BK][BN];

    int tid = threadIdx.x;
    int tx = tid & 15;            // 0..15 -> n block of 4
    int ty = tid >> 4;            // 0..15 -> m block of 8
    int mBase = blockIdx.y * BM;
    int nBase = blockIdx.x * BN;

    float acc[8][4];
#pragma unroll
    for (int m = 0; m < 8; ++m)
#pragma unroll
        for (int n = 0; n < 4; ++n) acc[m][n] = 0.f;

    int npairs = (A2 != nullptr) ? 2 : 1;
    for (int p = 0; p < npairs; ++p) {
        const float* A  = p ? A2 : A1;
        const float* Bw = p ? B2 : B1;
        for (int k0 = 0; k0 < HID; k0 += BK) {
            // A tile: 128 rows x 16 cols, stored transposed in smem
#pragma unroll
            for (int q = 0; q < 2; ++q) {
                int i = tid * 2 + q;
                int row = i >> 2;
                int kk = (i & 3) * 4;
                float4 v = *(const float4*)&A[(size_t)(mBase + row) * HID + k0 + kk];
                As[kk + 0][row] = v.x;
                As[kk + 1][row] = v.y;
                As[kk + 2][row] = v.z;
                As[kk + 3][row] = v.w;
            }
            // B tile: 16 rows x 64 cols
            {
                int krow = tid >> 4;
                int nn = (tid & 15) * 4;
                *(float4*)&Bs[krow][nn] =
                    *(const float4*)&Bw[(size_t)(k0 + krow) * HID + nBase + nn];
            }
            __syncthreads();
#pragma unroll
            for (int k = 0; k < BK; ++k) {
                float4 a0 = *(float4*)&As[k][ty * 8];
                float4 a1 = *(float4*)&As[k][ty * 8 + 4];
                float4 b0 = *(float4*)&Bs[k][tx * 4];
                float a[8] = {a0.x, a0.y, a0.z, a0.w, a1.x, a1.y, a1.z, a1.w};
                float b[4] = {b0.x, b0.y, b0.z, b0.w};
#pragma unroll
                for (int m = 0; m < 8; ++m)
#pragma unroll
                    for (int n = 0; n < 4; ++n)
                        acc[m][n] += a[m] * b[n];
            }
            __syncthreads();
        }
    }

    // epilogue: bias + activation, vectorized store
    float bfrag[4];
#pragma unroll
    for (int n = 0; n < 4; ++n) bfrag[n] = bias[nBase + tx * 4 + n];
#pragma unroll
    for (int m = 0; m < 8; ++m) {
        int gm = mBase + ty * 8 + m;
        float4 outv;
        float* o = (float*)&outv;
#pragma unroll
        for (int n = 0; n < 4; ++n) {
            float v = acc[m][n] + bfrag[n];
            if (act == 1)      v = tanhf(v);
            else if (act == 2) v = fmaxf(v, 0.f);
            o[n] = v;
        }
        *(float4*)&C[(size_t)gm * HID + nBase + tx * 4] = outv;
    }
}

// out[b, t, :] = tanh(r[b] @ W2^T + b2)  — one warp per batch row
__global__ void head2_kernel(const float* __restrict__ r, const float* __restrict__ W2,
                             const float* __restrict__ b2, float* __restrict__ out, int t) {
    int warp = (blockIdx.x * blockDim.x + threadIdx.x) >> 5;
    int lane = threadIdx.x & 31;
    if (warp >= BATCH) return;
    const float* rr = &r[(size_t)warp * HID];
    float s0 = 0.f, s1 = 0.f;
#pragma unroll
    for (int k = lane; k < HID; k += 32) {
        float v = rr[k];
        s0 += v * W2[k];
        s1 += v * W2[HID + k];
    }
#pragma unroll
    for (int off = 16; off; off >>= 1) {
        s0 += __shfl_down_sync(0xffffffffu, s0, off);
        s1 += __shfl_down_sync(0xffffffffu, s1, off);
    }
    if (lane == 0) {
        out[(size_t)warp * (TDEC * 2) + t * 2 + 0] = tanhf(s0 + b2[0]);
        out[(size_t)warp * (TDEC * 2) + t * 2 + 1] = tanhf(s1 + b2[1]);
    }
}

// ---------------- launch ------------------------------------------------------
extern "C" void kernel_launch(void* const* d_in, const int* in_sizes, int n_in,
                              void* d_out, int out_size) {
    (void)in_sizes; (void)n_in; (void)out_size;
    const float* x       = (const float*)d_in[0];
    const float* emW     = (const float*)d_in[1];
    const float* emb     = (const float*)d_in[2];
    const float* evW     = (const float*)d_in[3];
    const float* evb     = (const float*)d_in[4];
    const float* encWih  = (const float*)d_in[5];
    const float* encWhh  = (const float*)d_in[6];
    const float* encbih  = (const float*)d_in[7];
    const float* encbhh  = (const float*)d_in[8];
    const float* decWih  = (const float*)d_in[9];
    const float* decWhh  = (const float*)d_in[10];
    const float* decbih  = (const float*)d_in[11];
    const float* decbhh  = (const float*)d_in[12];
    const float* headW1  = (const float*)d_in[13];
    const float* headb1  = (const float*)d_in[14];
    const float* headW2  = (const float*)d_in[15];
    const float* headb2  = (const float*)d_in[16];
    float* out = (float*)d_out;

    float *hbuf, *xt, *relu, *wt, *bias;
    cudaGetSymbolAddress((void**)&hbuf, g_h);
    cudaGetSymbolAddress((void**)&xt,   g_xt);
    cudaGetSymbolAddress((void**)&relu, g_relu);
    cudaGetSymbolAddress((void**)&wt,   g_WT);
    cudaGetSymbolAddress((void**)&bias, g_bias);

    float* hP[2][2];
    for (int p = 0; p < 2; ++p)
        for (int l = 0; l < 2; ++l)
            hP[p][l] = hbuf + (size_t)(p * 2 + l) * BATCH * HID;
    float* WT[9];
    for (int m = 0; m < 9; ++m) WT[m] = wt + (size_t)m * HID * HID;

    const size_t MM = (size_t)HID * HID;
    Ptr9 src;
    src.p[0] = encWih;            // enc Wih l0
    src.p[1] = encWhh;            // enc Whh l0
    src.p[2] = encWih + MM;       // enc Wih l1
    src.p[3] = encWhh + MM;       // enc Whh l1
    src.p[4] = decWih;
    src.p[5] = decWhh;
    src.p[6] = decWih + MM;
    src.p[7] = decWhh + MM;
    src.p[8] = headW1;

    // init: zero parity-0 hidden state, prep transposed weights + summed biases
    zero_kernel<<<512, 256>>>(hbuf, 2 * BATCH * HID);
    transpose_kernel<<<dim3(16, 16, 9), dim3(32, 8)>>>(src, wt);
    bias_kernel<<<8, 256>>>(encbih, encbhh, decbih, decbhh, bias);

    dim3 ggrid(HID / BN, BATCH / BM);   // (8, 32)
    int s = 0;

    // ---- encoder: 33 steps ----
    for (int t = 0; t < SEQLEN; ++t) {
        int p = s & 1, q = p ^ 1;
        embed_kernel<<<BATCH, HID>>>(x, emW, emb, evW, evb, t, xt);
        // layer 0: tanh(xt@Wih0^T + h[p][0]@Whh0^T + b0)
        gemm_kernel<<<ggrid, 256>>>(xt, WT[0], hP[p][0], WT[1], bias + 0 * HID, hP[q][0], 1);
        // layer 1: tanh(h[q][0]@Wih1^T + h[p][1]@Whh1^T + b1)
        gemm_kernel<<<ggrid, 256>>>(hP[q][0], WT[2], hP[p][1], WT[3], bias + 1 * HID, hP[q][1], 1);
        s++;
    }

    // ---- decoder: 60 steps (input = previous top = h[p][1]) ----
    for (int k = 0; k < TDEC; ++k) {
        int p = s & 1, q = p ^ 1;
        gemm_kernel<<<ggrid, 256>>>(hP[p][1], WT[4], hP[p][0], WT[5], bias + 2 * HID, hP[q][0], 1);
        gemm_kernel<<<ggrid, 256>>>(hP[q][0], WT[6], hP[p][1], WT[7], bias + 3 * HID, hP[q][1], 1);
        // head hidden: relu(top@W1^T + b1)
        gemm_kernel<<<ggrid, 256>>>(hP[q][1], WT[8], nullptr, nullptr, headb1, relu, 2);
        head2_kernel<<<512, 256>>>(relu, headW2, headb2, out, k);
        s++;
    }
}